// round 4
// baseline (speedup 1.0000x reference)
#include <cuda_runtime.h>
#include <math.h>

#define B_   32
#define F_   256
#define T_   4096
#define NPB  (F_ * T_)
#define PADL 256
#define TF   16
#define TT   64

// Scratch: blurred field [B, F, T] fp32 (134 MB), per-batch min/max keys.
__device__ float    g_blur[(size_t)B_ * NPB];
__device__ unsigned g_mx1[B_], g_mn1[B_], g_mx2[B_], g_mn2[B_];

// Order-preserving float<->uint mapping for atomic min/max.
__device__ __forceinline__ unsigned fkey(float f) {
    unsigned u = __float_as_uint(f);
    return (u & 0x80000000u) ? ~u : (u | 0x80000000u);
}
__device__ __forceinline__ float funkey(unsigned k) {
    unsigned u = (k & 0x80000000u) ? (k & 0x7fffffffu) : ~k;
    return __uint_as_float(u);
}
// jnp.pad mode='reflect' index mapping (no edge duplication), valid for |overhang| <= n-1.
__device__ __forceinline__ int refl(int i, int n) {
    i = (i < 0) ? -i : i;
    i = (i >= n) ? (2 * n - 2 - i) : i;
    return i;
}

__global__ void init_k() {
    int i = threadIdx.x;
    if (i < B_) {
        g_mx1[i] = 0u;          g_mn1[i] = 0xFFFFFFFFu;
        g_mx2[i] = 0u;          g_mn2[i] = 0xFFFFFFFFu;
    }
}

// Stage A: per-batch min/max of the raw input. grid = (64, B_), 256 threads.
__global__ void minmax1_k(const float* __restrict__ in) {
    int b = blockIdx.y;
    const float4* p = (const float4*)(in + (size_t)b * NPB);
    int stride = gridDim.x * blockDim.x;
    int t = blockIdx.x * blockDim.x + threadIdx.x;
    float mx = -INFINITY, mn = INFINITY;
    for (int i = t; i < NPB / 4; i += stride) {
        float4 v = p[i];
        mx = fmaxf(mx, fmaxf(fmaxf(v.x, v.y), fmaxf(v.z, v.w)));
        mn = fminf(mn, fminf(fminf(v.x, v.y), fminf(v.z, v.w)));
    }
#pragma unroll
    for (int o = 16; o > 0; o >>= 1) {
        mx = fmaxf(mx, __shfl_xor_sync(0xffffffffu, mx, o));
        mn = fminf(mn, __shfl_xor_sync(0xffffffffu, mn, o));
    }
    __shared__ float smx[8], smn[8];
    int lane = threadIdx.x & 31, w = threadIdx.x >> 5;
    if (lane == 0) { smx[w] = mx; smn[w] = mn; }
    __syncthreads();
    if (threadIdx.x == 0) {
        for (int i = 1; i < (int)(blockDim.x >> 5); i++) {
            mx = fmaxf(mx, smx[i]); mn = fminf(mn, smn[i]);
        }
        atomicMax(&g_mx1[b], fkey(mx));
        atomicMin(&g_mn1[b], fkey(mn));
    }
}

// Stage B: fused peak1 -> normalize -> gaussian blur (freq conv then time conv,
// matching reference op order), writes blurred field, accumulates per-batch
// min/max of the blurred field via one atomic pair per block.
// grid = (T/TT, F/TF, B), block = (TT, TF) = (64, 16).
__global__ __launch_bounds__(1024)
void blur_k(const float* __restrict__ in, float gw0, float gw1, float gw2) {
    __shared__ float f_s [TF + 6][TT + 8];   // raw input, halo 3, -inf outside array
    __shared__ float p1_s[TF + 4][TT + 8];   // peak1 values, halo 2 (actual coords)
    __shared__ float tmp_s[TF][TT + 8];      // freq-blurred, time halo 2
    __shared__ float smx[32], smn[32];

    const int b   = blockIdx.z;
    const int fr0 = blockIdx.y * TF;
    const int t0  = blockIdx.x * TT;
    const int tid = threadIdx.y * TT + threadIdx.x;
    const float* fin = in + (size_t)b * NPB;
    const float gw[5] = {gw0, gw1, gw2, gw1, gw0};

    // Load input tile with halo 3; out-of-array -> -inf (SAME padding for the peak test).
    for (int i = tid; i < (TF + 6) * (TT + 6); i += 1024) {
        int ry = i / (TT + 6), rx = i % (TT + 6);
        int ar = fr0 - 3 + ry, ac = t0 - 3 + rx;
        float v = -INFINITY;
        if (ar >= 0 && ar < F_ && ac >= 0 && ac < T_) v = fin[ar * T_ + ac];
        f_s[ry][rx] = v;
    }
    __syncthreads();

    const float mn1 = funkey(g_mn1[b]);
    const float rng1 = funkey(g_mx1[b]) - mn1;

    // peak1 + normalize on actual coords [fr0-2, fr0+TF+1] x [t0-2, t0+TT+1].
    for (int i = tid; i < (TF + 4) * (TT + 4); i += 1024) {
        int ry = i / (TT + 4), rx = i % (TT + 4);
        int ar = fr0 - 2 + ry, ac = t0 - 2 + rx;
        float p = 0.f;
        if (ar >= 0 && ar < F_ && ac >= 0 && ac < T_) {
            float v = f_s[ry + 1][rx + 1];
            bool m = (v >= f_s[ry][rx + 1]) && (v >= f_s[ry + 2][rx + 1]) &&
                     (v >= f_s[ry + 1][rx]) && (v >= f_s[ry + 1][rx + 2]);
            p = m ? __fdiv_rn(v - mn1, rng1) : 0.f;
        }
        p1_s[ry][rx] = p;
    }
    __syncthreads();

    // Freq blur first (reference applies kf then kt). Reflect indices always
    // land inside the halo-2 p1 window.
    for (int i = tid; i < TF * (TT + 4); i += 1024) {
        int y = i / (TT + 4), rx = i % (TT + 4);
        int gy = fr0 + y;
        float acc = 0.f;
#pragma unroll
        for (int d = 0; d < 5; d++) {
            int slot = refl(gy + d - 2, F_) - (fr0 - 2);
            acc = fmaf(gw[d], p1_s[slot][rx], acc);
        }
        tmp_s[y][rx] = acc;
    }
    __syncthreads();

    // Time blur -> one output per thread.
    const int y = threadIdx.y, x = threadIdx.x;
    const int gx = t0 + x;
    float acc = 0.f;
#pragma unroll
    for (int d = 0; d < 5; d++) {
        int slot = refl(gx + d - 2, T_) - (t0 - 2);
        acc = fmaf(gw[d], tmp_s[y][slot], acc);
    }
    g_blur[(size_t)b * NPB + (size_t)(fr0 + y) * T_ + gx] = acc;

    // Fused per-batch min/max of the blurred field.
    float bmx = acc, bmn = acc;
#pragma unroll
    for (int o = 16; o > 0; o >>= 1) {
        bmx = fmaxf(bmx, __shfl_xor_sync(0xffffffffu, bmx, o));
        bmn = fminf(bmn, __shfl_xor_sync(0xffffffffu, bmn, o));
    }
    int lane = tid & 31, w = tid >> 5;
    if (lane == 0) { smx[w] = bmx; smn[w] = bmn; }
    __syncthreads();
    if (tid < 32) {
        bmx = smx[tid]; bmn = smn[tid];
#pragma unroll
        for (int o = 16; o > 0; o >>= 1) {
            bmx = fmaxf(bmx, __shfl_xor_sync(0xffffffffu, bmx, o));
            bmn = fminf(bmn, __shfl_xor_sync(0xffffffffu, bmn, o));
        }
        if (tid == 0) {
            atomicMax(&g_mx2[b], fkey(bmx));
            atomicMin(&g_mn2[b], fkey(bmn));
        }
    }
}

// Stage D: peak2 + ordered compaction of the first PADL positives per batch.
// One 1024-thread block per batch; early exit once 256 entries are placed.
__global__ __launch_bounds__(1024)
void extract_k(float* __restrict__ out) {
    const int b = blockIdx.x;
    const float* bl = g_blur + (size_t)b * NPB;
    const float mn2 = funkey(g_mn2[b]);
    const float rng2 = funkey(g_mx2[b]) - mn2;
    float* ob = out + b * 3 * PADL;
    const int tid = threadIdx.x;
    const int lane = tid & 31, w = tid >> 5;

    for (int i = tid; i < 3 * PADL; i += 1024) ob[i] = 0.f;

    __shared__ unsigned s_wc[32];
    __shared__ unsigned s_tot;
    __shared__ unsigned s_base;
    if (tid == 0) s_base = 0;
    __syncthreads();

    for (int chunk = 0; chunk < NPB / 1024; chunk++) {
        int idx = chunk * 1024 + tid;
        int y = idx >> 12;          // idx / T_
        int x = idx & (T_ - 1);
        float v  = bl[idx];
        float nU = (y > 0)      ? bl[idx - T_] : -INFINITY;
        float nD = (y < F_ - 1) ? bl[idx + T_] : -INFINITY;
        float nL = (x > 0)      ? bl[idx - 1]  : -INFINITY;
        float nR = (x < T_ - 1) ? bl[idx + 1]  : -INFINITY;
        bool m = (v >= nU) && (v >= nD) && (v >= nL) && (v >= nR);
        float val = m ? __fdiv_rn(v - mn2, rng2) : 0.f;
        bool pred = val > 0.f;

        unsigned bal = __ballot_sync(0xffffffffu, pred);
        if (lane == 0) s_wc[w] = (unsigned)__popc(bal);
        __syncthreads();
        if (tid == 0) {
            unsigned run = 0;
#pragma unroll
            for (int i = 0; i < 32; i++) { unsigned c = s_wc[i]; s_wc[i] = run; run += c; }
            s_tot = run;
        }
        __syncthreads();
        unsigned base = s_base;
        unsigned tot  = s_tot;
        if (pred) {
            unsigned slot = base + s_wc[w] + (unsigned)__popc(bal & ((1u << lane) - 1u));
            if (slot < PADL) {
                ob[slot]            = (float)y / (float)F_;
                ob[PADL + slot]     = (float)x / (float)T_;
                ob[2 * PADL + slot] = val;
            }
        }
        __syncthreads();
        if (tid == 0) s_base = base + tot;
        if (base + tot >= PADL) break;   // uniform decision
        __syncthreads();
    }
}

extern "C" void kernel_launch(void* const* d_in, const int* in_sizes, int n_in,
                              void* d_out, int out_size) {
    const float* in = (const float*)d_in[0];
    float* out = (float*)d_out;

    // Gaussian weights, fp32, same formula as the reference.
    float g[5];
    float s = 0.f;
    for (int i = 0; i < 5; i++) {
        float c = (float)(i - 2);
        g[i] = expf(-0.5f * c * c);
    }
    for (int i = 0; i < 5; i++) s += g[i];
    for (int i = 0; i < 5; i++) g[i] = g[i] / s;

    init_k<<<1, 32>>>();
    minmax1_k<<<dim3(64, B_), 256>>>(in);
    blur_k<<<dim3(T_ / TT, F_ / TF, B_), dim3(TT, TF)>>>(in, g[0], g[1], g[2]);
    extract_k<<<B_, 1024>>>(out);
}

// round 5
// speedup vs baseline: 2.5061x; 2.5061x over previous
#include <cuda_runtime.h>
#include <math.h>

#define B_   32
#define F_   256
#define T_   4096
#define NPB  (F_ * T_)
#define PADL 256

// blur tile
#define TF   16
#define TT   128
#define IH   (TF + 6)    // 22 input rows (halo 3)
#define IW   (TT + 6)    // 134 input cols
#define PH   (TF + 4)    // 20 p1 rows (halo 2)
#define PW   (TT + 4)    // 132 p1 cols
#define SW   136         // smem row stride (floats)

// Scratch: blurred field [B, F, T] fp32 (134 MB), per-batch min/max keys.
__device__ float    g_blur[(size_t)B_ * NPB];
__device__ unsigned g_mx1[B_], g_mn1[B_], g_mx2[B_], g_mn2[B_];

// Order-preserving float<->uint mapping for atomic min/max.
__device__ __forceinline__ unsigned fkey(float f) {
    unsigned u = __float_as_uint(f);
    return (u & 0x80000000u) ? ~u : (u | 0x80000000u);
}
__device__ __forceinline__ float funkey(unsigned k) {
    unsigned u = (k & 0x80000000u) ? (k & 0x7fffffffu) : ~k;
    return __uint_as_float(u);
}
// jnp.pad mode='reflect' index mapping (no edge duplication).
__device__ __forceinline__ int refl(int i, int n) {
    i = (i < 0) ? -i : i;
    i = (i >= n) ? (2 * n - 2 - i) : i;
    return i;
}

__global__ void init_k() {
    int i = threadIdx.x;
    if (i < B_) {
        g_mx1[i] = 0u;          g_mn1[i] = 0xFFFFFFFFu;
        g_mx2[i] = 0u;          g_mn2[i] = 0xFFFFFFFFu;
    }
}

// Stage A: per-batch min/max of the raw input. grid = (64, B_), 256 threads.
__global__ void minmax1_k(const float* __restrict__ in) {
    int b = blockIdx.y;
    const float4* p = (const float4*)(in + (size_t)b * NPB);
    int stride = gridDim.x * blockDim.x;
    int t = blockIdx.x * blockDim.x + threadIdx.x;
    float mx = -INFINITY, mn = INFINITY;
    for (int i = t; i < NPB / 4; i += stride) {
        float4 v = p[i];
        mx = fmaxf(mx, fmaxf(fmaxf(v.x, v.y), fmaxf(v.z, v.w)));
        mn = fminf(mn, fminf(fminf(v.x, v.y), fminf(v.z, v.w)));
    }
#pragma unroll
    for (int o = 16; o > 0; o >>= 1) {
        mx = fmaxf(mx, __shfl_xor_sync(0xffffffffu, mx, o));
        mn = fminf(mn, __shfl_xor_sync(0xffffffffu, mn, o));
    }
    __shared__ float smx[8], smn[8];
    int lane = threadIdx.x & 31, w = threadIdx.x >> 5;
    if (lane == 0) { smx[w] = mx; smn[w] = mn; }
    __syncthreads();
    if (threadIdx.x == 0) {
        for (int i = 1; i < (int)(blockDim.x >> 5); i++) {
            mx = fmaxf(mx, smx[i]); mn = fminf(mn, smn[i]);
        }
        atomicMax(&g_mx1[b], fkey(mx));
        atomicMin(&g_mn1[b], fkey(mn));
    }
}

// Stage B: fused peak1 -> normalize -> gaussian blur (freq conv then time conv),
// writes blurred field, per-batch min/max via one atomic pair per block.
// grid = (T/TT=32, F/TF=16, B), block = (32, 8) = 256 threads, 8 outputs/thread.
__global__ __launch_bounds__(256)
void blur_k(const float* __restrict__ in, float gw0, float gw1, float gw2) {
    __shared__ float f_s [IH][SW];   // raw input (halo 3), -inf outside the array
    __shared__ float p1_s[PH][SW];   // peak1-normalized (halo 2)
    __shared__ float tmp_s[TF][SW];  // freq-blurred (time halo 2)
    __shared__ float smx[8], smn[8];

    const int b   = blockIdx.z;
    const int fr0 = blockIdx.y * TF;
    const int t0  = blockIdx.x * TT;
    const int tx  = threadIdx.x;          // 0..31
    const int ty  = threadIdx.y;          // 0..7
    const int tid = ty * 32 + tx;
    const float* __restrict__ fin = in + (size_t)b * NPB;

    const bool int_f = (blockIdx.y > 0) && (blockIdx.y < gridDim.y - 1);
    const bool int_t = (blockIdx.x > 0) && (blockIdx.x < gridDim.x - 1);

    // ---- Load input tile with halo 3 ----
    if (int_f && int_t) {
#pragma unroll
        for (int r0 = 0; r0 < 3; r0++) {
            int r = ty + r0 * 8;
            if (r < IH) {
                const float* rp = fin + (size_t)(fr0 - 3 + r) * T_ + (t0 - 3);
#pragma unroll
                for (int c0 = 0; c0 < 5; c0++) {
                    int c = tx + c0 * 32;
                    if (c < IW) f_s[r][c] = rp[c];
                }
            }
        }
    } else {
#pragma unroll
        for (int r0 = 0; r0 < 3; r0++) {
            int r = ty + r0 * 8;
            if (r < IH) {
                int ar = fr0 - 3 + r;
                bool rok = (ar >= 0) && (ar < F_);
                const float* rp = fin + (size_t)(rok ? ar : 0) * T_;
#pragma unroll
                for (int c0 = 0; c0 < 5; c0++) {
                    int c = tx + c0 * 32;
                    if (c < IW) {
                        int ac = t0 - 3 + c;
                        float v = -INFINITY;
                        if (rok && ac >= 0 && ac < T_) v = rp[ac];
                        f_s[r][c] = v;
                    }
                }
            }
        }
    }
    __syncthreads();

    const float mn1  = funkey(g_mn1[b]);
    const float inv1 = 1.0f / (funkey(g_mx1[b]) - mn1);

    // ---- peak1 + normalize (halo-2 window; out-of-array slots written but never read) ----
#pragma unroll
    for (int r0 = 0; r0 < 3; r0++) {
        int r = ty + r0 * 8;
        if (r < PH) {
#pragma unroll
            for (int c0 = 0; c0 < 5; c0++) {
                int c = tx + c0 * 32;
                if (c < PW) {
                    float v = f_s[r + 1][c + 1];
                    bool m = (v >= f_s[r][c + 1]) && (v >= f_s[r + 2][c + 1]) &&
                             (v >= f_s[r + 1][c]) && (v >= f_s[r + 1][c + 2]);
                    p1_s[r][c] = m ? (v - mn1) * inv1 : 0.f;
                }
            }
        }
    }
    __syncthreads();

    // ---- Freq blur (taps symmetric: gw0,gw1,gw2,gw1,gw0) ----
    if (int_f) {
#pragma unroll
        for (int r0 = 0; r0 < 2; r0++) {
            int r = ty + r0 * 8;   // output row; taps at p1 slots r..r+4
#pragma unroll
            for (int c0 = 0; c0 < 5; c0++) {
                int c = tx + c0 * 32;
                if (c < PW) {
                    float s0 = p1_s[r][c] + p1_s[r + 4][c];
                    float s1 = p1_s[r + 1][c] + p1_s[r + 3][c];
                    tmp_s[r][c] = fmaf(gw0, s0, fmaf(gw1, s1, gw2 * p1_s[r + 2][c]));
                }
            }
        }
    } else {
#pragma unroll
        for (int r0 = 0; r0 < 2; r0++) {
            int r = ty + r0 * 8;
            int gy = fr0 + r;
            int rs0 = refl(gy - 2, F_) - (fr0 - 2);
            int rs1 = refl(gy - 1, F_) - (fr0 - 2);
            int rs2 = r + 2;
            int rs3 = refl(gy + 1, F_) - (fr0 - 2);
            int rs4 = refl(gy + 2, F_) - (fr0 - 2);
#pragma unroll
            for (int c0 = 0; c0 < 5; c0++) {
                int c = tx + c0 * 32;
                if (c < PW) {
                    float acc = gw0 * p1_s[rs0][c];
                    acc = fmaf(gw1, p1_s[rs1][c], acc);
                    acc = fmaf(gw2, p1_s[rs2][c], acc);
                    acc = fmaf(gw1, p1_s[rs3][c], acc);
                    acc = fmaf(gw0, p1_s[rs4][c], acc);
                    tmp_s[r][c] = acc;
                }
            }
        }
    }
    __syncthreads();

    // ---- Time blur -> global, fused per-batch min/max ----
    float bmx = -INFINITY, bmn = INFINITY;
    float* gout = g_blur + (size_t)b * NPB;
    if (int_t) {
#pragma unroll
        for (int r0 = 0; r0 < 2; r0++) {
            int r = ty + r0 * 8;
            float* orow = gout + (size_t)(fr0 + r) * T_ + t0;
#pragma unroll
            for (int c0 = 0; c0 < 4; c0++) {
                int c = tx + c0 * 32;    // taps at tmp slots c..c+4
                float s0 = tmp_s[r][c] + tmp_s[r][c + 4];
                float s1 = tmp_s[r][c + 1] + tmp_s[r][c + 3];
                float acc = fmaf(gw0, s0, fmaf(gw1, s1, gw2 * tmp_s[r][c + 2]));
                orow[c] = acc;
                bmx = fmaxf(bmx, acc); bmn = fminf(bmn, acc);
            }
        }
    } else {
#pragma unroll
        for (int r0 = 0; r0 < 2; r0++) {
            int r = ty + r0 * 8;
            float* orow = gout + (size_t)(fr0 + r) * T_ + t0;
#pragma unroll
            for (int c0 = 0; c0 < 4; c0++) {
                int c = tx + c0 * 32;
                int gx = t0 + c;
                int cs0 = refl(gx - 2, T_) - (t0 - 2);
                int cs1 = refl(gx - 1, T_) - (t0 - 2);
                int cs3 = refl(gx + 1, T_) - (t0 - 2);
                int cs4 = refl(gx + 2, T_) - (t0 - 2);
                float acc = gw0 * tmp_s[r][cs0];
                acc = fmaf(gw1, tmp_s[r][cs1], acc);
                acc = fmaf(gw2, tmp_s[r][c + 2], acc);
                acc = fmaf(gw1, tmp_s[r][cs3], acc);
                acc = fmaf(gw0, tmp_s[r][cs4], acc);
                orow[c] = acc;
                bmx = fmaxf(bmx, acc); bmn = fminf(bmn, acc);
            }
        }
    }

#pragma unroll
    for (int o = 16; o > 0; o >>= 1) {
        bmx = fmaxf(bmx, __shfl_xor_sync(0xffffffffu, bmx, o));
        bmn = fminf(bmn, __shfl_xor_sync(0xffffffffu, bmn, o));
    }
    int lane = tid & 31, w = tid >> 5;
    if (lane == 0) { smx[w] = bmx; smn[w] = bmn; }
    __syncthreads();
    if (tid == 0) {
        bmx = smx[0]; bmn = smn[0];
#pragma unroll
        for (int i = 1; i < 8; i++) {
            bmx = fmaxf(bmx, smx[i]); bmn = fminf(bmn, smn[i]);
        }
        atomicMax(&g_mx2[b], fkey(bmx));
        atomicMin(&g_mn2[b], fkey(bmn));
    }
}

// Stage D: peak2 + ordered compaction of the first PADL positives per batch.
// One 1024-thread block per batch; early exit once 256 entries are placed.
__global__ __launch_bounds__(1024)
void extract_k(float* __restrict__ out) {
    const int b = blockIdx.x;
    const float* bl = g_blur + (size_t)b * NPB;
    const float mn2 = funkey(g_mn2[b]);
    const float rng2 = funkey(g_mx2[b]) - mn2;
    float* ob = out + b * 3 * PADL;
    const int tid = threadIdx.x;
    const int lane = tid & 31, w = tid >> 5;

    for (int i = tid; i < 3 * PADL; i += 1024) ob[i] = 0.f;

    __shared__ unsigned s_wc[32];
    __shared__ unsigned s_tot;
    __shared__ unsigned s_base;
    if (tid == 0) s_base = 0;
    __syncthreads();

    for (int chunk = 0; chunk < NPB / 1024; chunk++) {
        int idx = chunk * 1024 + tid;
        int y = idx >> 12;          // idx / T_
        int x = idx & (T_ - 1);
        float v  = bl[idx];
        float nU = (y > 0)      ? bl[idx - T_] : -INFINITY;
        float nD = (y < F_ - 1) ? bl[idx + T_] : -INFINITY;
        float nL = (x > 0)      ? bl[idx - 1]  : -INFINITY;
        float nR = (x < T_ - 1) ? bl[idx + 1]  : -INFINITY;
        bool m = (v >= nU) && (v >= nD) && (v >= nL) && (v >= nR);
        float val = m ? __fdiv_rn(v - mn2, rng2) : 0.f;
        bool pred = val > 0.f;

        unsigned bal = __ballot_sync(0xffffffffu, pred);
        if (lane == 0) s_wc[w] = (unsigned)__popc(bal);
        __syncthreads();
        if (tid == 0) {
            unsigned run = 0;
#pragma unroll
            for (int i = 0; i < 32; i++) { unsigned c = s_wc[i]; s_wc[i] = run; run += c; }
            s_tot = run;
        }
        __syncthreads();
        unsigned base = s_base;
        unsigned tot  = s_tot;
        if (pred) {
            unsigned slot = base + s_wc[w] + (unsigned)__popc(bal & ((1u << lane) - 1u));
            if (slot < PADL) {
                ob[slot]            = (float)y / (float)F_;
                ob[PADL + slot]     = (float)x / (float)T_;
                ob[2 * PADL + slot] = val;
            }
        }
        __syncthreads();
        if (tid == 0) s_base = base + tot;
        if (base + tot >= PADL) break;   // uniform decision
        __syncthreads();
    }
}

extern "C" void kernel_launch(void* const* d_in, const int* in_sizes, int n_in,
                              void* d_out, int out_size) {
    const float* in = (const float*)d_in[0];
    float* out = (float*)d_out;

    // Gaussian weights, fp32, same formula as the reference.
    float g[5];
    float s = 0.f;
    for (int i = 0; i < 5; i++) {
        float c = (float)(i - 2);
        g[i] = expf(-0.5f * c * c);
    }
    for (int i = 0; i < 5; i++) s += g[i];
    for (int i = 0; i < 5; i++) g[i] = g[i] / s;

    init_k<<<1, 32>>>();
    minmax1_k<<<dim3(64, B_), 256>>>(in);
    blur_k<<<dim3(T_ / TT, F_ / TF, B_), dim3(32, 8)>>>(in, g[0], g[1], g[2]);
    extract_k<<<B_, 1024>>>(out);
}